// round 2
// baseline (speedup 1.0000x reference)
#include <cuda_runtime.h>
#include <math.h>

#define SS 512
#define PP 64
#define TT 8
#define NN (SS*PP)            // 32768

#define ENC_ELEMS (NN*72)     // 2359296
#define SEQ_ELEMS (TT*NN*32)  // 8388608

__device__ float g_graph_in[SEQ_ELEMS];        // GAT output -> graph LSTM input
__device__ float g_x2[(size_t)SS*TT*64*64];    // GAT layer0 output (elu'd)
__device__ float g_traj_fb[SEQ_ELEMS];
__device__ float g_graph_fb[SEQ_ELEMS];

__device__ __forceinline__ float tanh_fast(float x){
    float y; asm("tanh.approx.f32 %0, %1;" : "=f"(y) : "f"(x)); return y;
}
__device__ __forceinline__ float sig_fast(float x){
    return 0.5f * tanh_fast(0.5f * x) + 0.5f;
}
__device__ __forceinline__ void fma4(float4& a, float s, const float4 w){
    a.x += s*w.x; a.y += s*w.y; a.z += s*w.z; a.w += s*w.w;
}

// ---------------------------------------------------------------------------
// LSTM traj: input dim 3, hidden 32, T=8. Warp = 4 peds, lane = hidden unit.
// Weights packed float4 by gate: sWhh4[k*32+lane] = {Wi,Wf,Wg,Wo rows at lane}.
// ---------------------------------------------------------------------------
__global__ void lstm_traj_kernel(const float* __restrict__ x,
        const float* __restrict__ h0, const float* __restrict__ c0,
        const float* __restrict__ Wih, const float* __restrict__ Whh,
        const float* __restrict__ bih, const float* __restrict__ bhh,
        float* __restrict__ hs)
{
    __shared__ __align__(16) float4 sWhh4[1024];  // [k][lane] -> gates
    __shared__ __align__(16) float4 sWihP[96];    // [j][lane] -> gates (j=0..2)
    __shared__ __align__(16) float4 sb4[32];      // [lane] -> gates
    const int tid = threadIdx.x;

    for (int i = tid; i < 4096; i += 256) {
        int r = i >> 5, k = i & 31;
        ((float*)sWhh4)[(k*32 + (r & 31))*4 + (r >> 5)] = Whh[i];
    }
    for (int i = tid; i < 384; i += 256) {
        int r = i / 3, j = i - r*3;
        ((float*)sWihP)[(j*32 + (r & 31))*4 + (r >> 5)] = Wih[i];
    }
    if (tid < 32) {
        float4 b;
        b.x = bih[tid]      + bhh[tid];
        b.y = bih[32 + tid] + bhh[32 + tid];
        b.z = bih[64 + tid] + bhh[64 + tid];
        b.w = bih[96 + tid] + bhh[96 + tid];
        sb4[tid] = b;
    }
    __syncthreads();

    const int lane = tid & 31;
    const int n0 = blockIdx.x * 32 + (tid >> 5) * 4;

    float h[4], c[4];
    #pragma unroll
    for (int r = 0; r < 4; r++) { h[r] = h0[(n0+r)*32 + lane]; c[r] = c0[(n0+r)*32 + lane]; }

    #pragma unroll
    for (int t = 0; t < TT; t++) {
        float4 a[4];
        const float4 w0 = sWihP[lane], w1 = sWihP[32 + lane], w2 = sWihP[64 + lane];
        const float4 bb = sb4[lane];
        #pragma unroll
        for (int r = 0; r < 4; r++) {
            const float* xp = x + ((size_t)t*NN + n0 + r) * 3;
            float x0 = xp[0], x1 = xp[1], x2 = xp[2];
            a[r] = bb;
            fma4(a[r], x0, w0); fma4(a[r], x1, w1); fma4(a[r], x2, w2);
        }
        #pragma unroll
        for (int k = 0; k < 32; k++) {
            float4 w = sWhh4[k*32 + lane];
            #pragma unroll
            for (int r = 0; r < 4; r++) {
                float hk = __shfl_sync(0xffffffffu, h[r], k);
                fma4(a[r], hk, w);
            }
        }
        #pragma unroll
        for (int r = 0; r < 4; r++) {
            c[r] = sig_fast(a[r].y) * c[r] + sig_fast(a[r].x) * tanh_fast(a[r].z);
            h[r] = sig_fast(a[r].w) * tanh_fast(c[r]);
            hs[((size_t)t*NN + n0 + r)*32 + lane] = h[r];
        }
    }
}

// ---------------------------------------------------------------------------
// GAT layer 0: one block per (scene, timestep) graph.
// ---------------------------------------------------------------------------
__global__ void gat0_kernel(const float* __restrict__ traj,
        const float* __restrict__ w0, const float* __restrict__ as0,
        const float* __restrict__ ad0, const float* __restrict__ b0)
{
    __shared__ __align__(16) float pool[4096];  // [0:2048)=x, [2048:4096)=w; later attn[64][64]
    __shared__ __align__(16) float shp[4096];   // hp[p][h*16+o]
    __shared__ float sS[256], sD[256];
    __shared__ __align__(16) float smean[32], sinv[32];
    __shared__ float srinv[64];
    __shared__ float sas[64], sad[64];
    __shared__ __align__(16) float4 sb0v[4];

    float4* sx4 = (float4*)pool;            // 512 float4
    float4* sw4 = (float4*)(pool + 2048);   // 512 float4: w(h,f,o4) at h*128+f*4+o4
    const int tid = threadIdx.x;
    const int b = blockIdx.x, sIdx = b >> 3, tIdx = b & 7;

    {
        const float4* src = (const float4*)(traj + ((size_t)tIdx*NN + sIdx*64) * 32);
        for (int i = tid; i < 512; i += 256) sx4[i] = src[i];
        const float4* wsrc = (const float4*)w0;
        for (int i = tid; i < 512; i += 256) sw4[i] = wsrc[i];
        if (tid < 64) { sas[tid] = as0[tid]; sad[tid] = ad0[tid]; }
        if (tid < 4)  sb0v[tid] = ((const float4*)b0)[tid];
    }
    __syncthreads();

    // instance norm stats over p per feature
    if (tid < 32) {
        const float* xs = pool;
        float s = 0.f, s2 = 0.f;
        for (int p = 0; p < 64; p++) { float v = xs[p*32 + tid]; s += v; s2 += v*v; }
        float m = s * (1.0f/64.0f);
        float var = s2 * (1.0f/64.0f) - m*m;
        smean[tid] = m; sinv[tid] = rsqrtf(var + 1e-5f);
    }
    __syncthreads();
    for (int i = tid; i < 512; i += 256) {
        int f4 = i & 7;
        float4 m4 = ((float4*)smean)[f4], i4 = ((float4*)sinv)[f4];
        float4 v = sx4[i];
        v.x = (v.x - m4.x)*i4.x; v.y = (v.y - m4.y)*i4.y;
        v.z = (v.z - m4.z)*i4.z; v.w = (v.w - m4.w)*i4.w;
        sx4[i] = v;
    }
    __syncthreads();

    // hp[p][hh*16 + o4*4 + e] : 1024 items of 4 outputs
    for (int it = tid; it < 1024; it += 256) {
        int p = it >> 4, j = it & 15, hh = j >> 2, o4 = j & 3;
        float4 acc = {0.f,0.f,0.f,0.f};
        #pragma unroll
        for (int f4 = 0; f4 < 8; f4++) {
            float4 xv = sx4[p*8 + f4];
            fma4(acc, xv.x, sw4[hh*128 + (f4*4+0)*4 + o4]);
            fma4(acc, xv.y, sw4[hh*128 + (f4*4+1)*4 + o4]);
            fma4(acc, xv.z, sw4[hh*128 + (f4*4+2)*4 + o4]);
            fma4(acc, xv.w, sw4[hh*128 + (f4*4+3)*4 + o4]);
        }
        ((float4*)shp)[p*16 + hh*4 + o4] = acc;
    }
    __syncthreads();

    // s[h][p], d[h][p]
    {
        int hh = tid >> 6, p = tid & 63;
        const float4* hp4 = (const float4*)shp;
        float as = 0.f, ad = 0.f;
        #pragma unroll
        for (int o4 = 0; o4 < 4; o4++) {
            float4 v = hp4[p*16 + hh*4 + o4];
            int ob = hh*16 + o4*4;
            as += v.x*sas[ob] + v.y*sas[ob+1] + v.z*sas[ob+2] + v.w*sas[ob+3];
            ad += v.x*sad[ob] + v.y*sad[ob+1] + v.z*sad[ob+2] + v.w*sad[ob+3];
        }
        sS[tid] = as; sD[tid] = ad;
    }
    __syncthreads();

    float* sattn = pool;  // [64][64], overlays x+w (both dead)

    for (int hh = 0; hh < 4; hh++) {
        // softmax: 4 threads per row
        {
            int p = tid >> 2, q = tid & 3;
            float sp = sS[hh*64 + p];
            float l[16]; float mx = -1e30f;
            #pragma unroll
            for (int mm = 0; mm < 16; mm++) {
                float v = sp + sD[hh*64 + q*16 + mm];
                v = (v > 0.f) ? v : 0.2f*v;
                l[mm] = v; mx = fmaxf(mx, v);
            }
            mx = fmaxf(mx, __shfl_xor_sync(0xffffffffu, mx, 1));
            mx = fmaxf(mx, __shfl_xor_sync(0xffffffffu, mx, 2));
            float sum = 0.f;
            #pragma unroll
            for (int mm = 0; mm < 16; mm++) {
                float e = __expf(l[mm] - mx);
                sattn[p*64 + q*16 + mm] = e; sum += e;
            }
            sum += __shfl_xor_sync(0xffffffffu, sum, 1);
            sum += __shfl_xor_sync(0xffffffffu, sum, 2);
            if (q == 0) srinv[p] = 1.0f / sum;
        }
        __syncthreads();
        // apply: thread = (p, o4)
        {
            int p = tid >> 2, o4 = tid & 3;
            const float* ap = &sattn[p*64];
            const float4* hp4 = (const float4*)shp;
            float4 acc = {0.f,0.f,0.f,0.f};
            #pragma unroll
            for (int m = 0; m < 64; m++) fma4(acc, ap[m], hp4[m*16 + hh*4 + o4]);
            float ri = srinv[p];
            float4 bb = sb0v[o4];
            float4 res;
            res.x = acc.x*ri + bb.x; res.y = acc.y*ri + bb.y;
            res.z = acc.z*ri + bb.z; res.w = acc.w*ri + bb.w;
            res.x = (res.x > 0.f) ? res.x : (__expf(res.x) - 1.f);
            res.y = (res.y > 0.f) ? res.y : (__expf(res.y) - 1.f);
            res.z = (res.z > 0.f) ? res.z : (__expf(res.z) - 1.f);
            res.w = (res.w > 0.f) ? res.w : (__expf(res.w) - 1.f);
            ((float4*)g_x2)[((size_t)b*64 + p)*16 + hh*4 + o4] = res;
        }
        __syncthreads();
    }
}

// ---------------------------------------------------------------------------
// GAT layer 1: x2[64,64] -> norm -> hp[64,32] -> attention -> g_graph_in
// ---------------------------------------------------------------------------
__global__ void gat1_kernel(const float* __restrict__ w1, const float* __restrict__ as1,
        const float* __restrict__ ad1, const float* __restrict__ b1)
{
    __shared__ __align__(16) float pool[4096];  // sx / sattn
    __shared__ __align__(16) float sw[2048];    // w(f,o4) at f*8+o4 (float4)
    __shared__ __align__(16) float shp[2048];
    __shared__ float sS[64], sD[64];
    __shared__ __align__(16) float smean[64], sinv[64];
    __shared__ float srinv[64], sas[32], sad[32];
    __shared__ __align__(16) float4 sb1v[8];

    float4* sx4 = (float4*)pool;          // 1024 float4
    float4* sw4 = (float4*)sw;            // 512 float4
    const int tid = threadIdx.x;
    const int b = blockIdx.x, sIdx = b >> 3, tIdx = b & 7;

    {
        const float4* src = (const float4*)(g_x2 + (size_t)b*4096);
        for (int i = tid; i < 1024; i += 256) sx4[i] = src[i];
        const float4* wsrc = (const float4*)w1;
        for (int i = tid; i < 512; i += 256) sw4[i] = wsrc[i];
        if (tid < 32) { sas[tid] = as1[tid]; sad[tid] = ad1[tid]; }
        if (tid < 8)  sb1v[tid] = ((const float4*)b1)[tid];
    }
    __syncthreads();

    if (tid < 64) {
        float s = 0.f, s2 = 0.f;
        for (int p = 0; p < 64; p++) { float v = pool[p*64 + tid]; s += v; s2 += v*v; }
        float m = s * (1.0f/64.0f);
        float var = s2 * (1.0f/64.0f) - m*m;
        smean[tid] = m; sinv[tid] = rsqrtf(var + 1e-5f);
    }
    __syncthreads();
    for (int i = tid; i < 1024; i += 256) {
        int f4 = i & 15;
        float4 m4 = ((float4*)smean)[f4], i4 = ((float4*)sinv)[f4];
        float4 v = sx4[i];
        v.x = (v.x - m4.x)*i4.x; v.y = (v.y - m4.y)*i4.y;
        v.z = (v.z - m4.z)*i4.z; v.w = (v.w - m4.w)*i4.w;
        sx4[i] = v;
    }
    __syncthreads();

    // hp: 512 items (p, o4), 2 per thread
    for (int it = tid; it < 512; it += 256) {
        int p = it >> 3, o4 = it & 7;
        float4 acc = {0.f,0.f,0.f,0.f};
        #pragma unroll
        for (int f4 = 0; f4 < 16; f4++) {
            float4 xv = sx4[p*16 + f4];
            fma4(acc, xv.x, sw4[(f4*4+0)*8 + o4]);
            fma4(acc, xv.y, sw4[(f4*4+1)*8 + o4]);
            fma4(acc, xv.z, sw4[(f4*4+2)*8 + o4]);
            fma4(acc, xv.w, sw4[(f4*4+3)*8 + o4]);
        }
        ((float4*)shp)[p*8 + o4] = acc;
    }
    __syncthreads();

    if (tid < 64) {
        int p = tid;
        const float4* hp4 = (const float4*)shp;
        float as = 0.f, ad = 0.f;
        #pragma unroll
        for (int o4 = 0; o4 < 8; o4++) {
            float4 v = hp4[p*8 + o4];
            as += v.x*sas[o4*4] + v.y*sas[o4*4+1] + v.z*sas[o4*4+2] + v.w*sas[o4*4+3];
            ad += v.x*sad[o4*4] + v.y*sad[o4*4+1] + v.z*sad[o4*4+2] + v.w*sad[o4*4+3];
        }
        sS[p] = as; sD[p] = ad;
    }
    __syncthreads();

    float* sattn = pool;  // overlays x (dead)
    {
        int p = tid >> 2, q = tid & 3;
        float sp = sS[p];
        float l[16]; float mx = -1e30f;
        #pragma unroll
        for (int mm = 0; mm < 16; mm++) {
            float v = sp + sD[q*16 + mm];
            v = (v > 0.f) ? v : 0.2f*v;
            l[mm] = v; mx = fmaxf(mx, v);
        }
        mx = fmaxf(mx, __shfl_xor_sync(0xffffffffu, mx, 1));
        mx = fmaxf(mx, __shfl_xor_sync(0xffffffffu, mx, 2));
        float sum = 0.f;
        #pragma unroll
        for (int mm = 0; mm < 16; mm++) {
            float e = __expf(l[mm] - mx);
            sattn[p*64 + q*16 + mm] = e; sum += e;
        }
        sum += __shfl_xor_sync(0xffffffffu, sum, 1);
        sum += __shfl_xor_sync(0xffffffffu, sum, 2);
        if (q == 0) srinv[p] = 1.0f / sum;
    }
    __syncthreads();

    for (int it = tid; it < 512; it += 256) {
        int p = it >> 3, o4 = it & 7;
        const float* ap = &sattn[p*64];
        const float4* hp4 = (const float4*)shp;
        float4 acc = {0.f,0.f,0.f,0.f};
        #pragma unroll
        for (int m = 0; m < 64; m++) fma4(acc, ap[m], hp4[m*8 + o4]);
        float ri = srinv[p];
        float4 bb = sb1v[o4];
        float4 res;
        res.x = acc.x*ri + bb.x; res.y = acc.y*ri + bb.y;
        res.z = acc.z*ri + bb.z; res.w = acc.w*ri + bb.w;
        ((float4*)g_graph_in)[((size_t)tIdx*NN + sIdx*64 + p)*8 + o4] = res;
    }
}

// ---------------------------------------------------------------------------
// LSTM graph: input dim 32, hidden 32, T=8. Warp = 4 peds.
// ---------------------------------------------------------------------------
__global__ void lstm_graph_kernel(
        const float* __restrict__ h0, const float* __restrict__ c0,
        const float* __restrict__ Wih, const float* __restrict__ Whh,
        const float* __restrict__ bih, const float* __restrict__ bhh,
        float* __restrict__ hs)
{
    __shared__ __align__(16) float4 sWih4[1024];
    __shared__ __align__(16) float4 sWhh4[1024];
    __shared__ __align__(16) float4 sb4[32];
    const int tid = threadIdx.x;

    for (int i = tid; i < 4096; i += 256) {
        int r = i >> 5, k = i & 31;
        int idx = (k*32 + (r & 31))*4 + (r >> 5);
        ((float*)sWih4)[idx] = Wih[i];
        ((float*)sWhh4)[idx] = Whh[i];
    }
    if (tid < 32) {
        float4 b;
        b.x = bih[tid]      + bhh[tid];
        b.y = bih[32 + tid] + bhh[32 + tid];
        b.z = bih[64 + tid] + bhh[64 + tid];
        b.w = bih[96 + tid] + bhh[96 + tid];
        sb4[tid] = b;
    }
    __syncthreads();

    const int lane = tid & 31;
    const int n0 = blockIdx.x * 32 + (tid >> 5) * 4;

    float h[4], c[4];
    #pragma unroll
    for (int r = 0; r < 4; r++) { h[r] = h0[(n0+r)*32 + lane]; c[r] = c0[(n0+r)*32 + lane]; }

    #pragma unroll
    for (int t = 0; t < TT; t++) {
        float4 a[4];
        float xv[4];
        const float4 bb = sb4[lane];
        #pragma unroll
        for (int r = 0; r < 4; r++) {
            xv[r] = g_graph_in[((size_t)t*NN + n0 + r)*32 + lane];
            a[r] = bb;
        }
        #pragma unroll
        for (int k = 0; k < 32; k++) {
            float4 wi = sWih4[k*32 + lane];
            float4 wh = sWhh4[k*32 + lane];
            #pragma unroll
            for (int r = 0; r < 4; r++) {
                float xk = __shfl_sync(0xffffffffu, xv[r], k);
                float hk = __shfl_sync(0xffffffffu, h[r],  k);
                fma4(a[r], xk, wi);
                fma4(a[r], hk, wh);
            }
        }
        #pragma unroll
        for (int r = 0; r < 4; r++) {
            c[r] = sig_fast(a[r].y) * c[r] + sig_fast(a[r].x) * tanh_fast(a[r].z);
            h[r] = sig_fast(a[r].w) * tanh_fast(c[r]);
            hs[((size_t)t*NN + n0 + r)*32 + lane] = h[r];
        }
    }
}

// ---------------------------------------------------------------------------
// Concat (float4): encoded[n] = [traj_hs[7,n] | graph_hs[7,n] | z[n/64]]
// ---------------------------------------------------------------------------
__global__ void concat_kernel(const float* __restrict__ z,
        const float* __restrict__ traj, const float* __restrict__ graph,
        float* __restrict__ out)
{
    int idx = blockIdx.x * blockDim.x + threadIdx.x;
    if (idx >= NN*18) return;
    int n = idx / 18, j = idx - n*18;
    float4 v;
    if (j < 8)       v = ((const float4*)traj)[((size_t)7*NN + n)*8 + j];
    else if (j < 16) v = ((const float4*)graph)[((size_t)7*NN + n)*8 + (j - 8)];
    else             v = ((const float4*)z)[(n >> 6)*2 + (j - 16)];
    ((float4*)out)[idx] = v;
}

extern "C" void kernel_launch(void* const* d_in, const int* in_sizes, int n_in,
                              void* d_out, int out_size) {
    const float* obs  = (const float*)d_in[0];
    const float* h0t  = (const float*)d_in[1];
    const float* c0t  = (const float*)d_in[2];
    const float* h0g  = (const float*)d_in[3];
    const float* c0g  = (const float*)d_in[4];
    const float* z    = (const float*)d_in[5];
    const float* WihT = (const float*)d_in[6];
    const float* WhhT = (const float*)d_in[7];
    const float* bihT = (const float*)d_in[8];
    const float* bhhT = (const float*)d_in[9];
    const float* WihG = (const float*)d_in[10];
    const float* WhhG = (const float*)d_in[11];
    const float* bihG = (const float*)d_in[12];
    const float* bhhG = (const float*)d_in[13];
    const float* w0   = (const float*)d_in[14];
    const float* as0  = (const float*)d_in[15];
    const float* ad0  = (const float*)d_in[16];
    const float* b0   = (const float*)d_in[17];
    const float* w1   = (const float*)d_in[18];
    const float* as1  = (const float*)d_in[19];
    const float* ad1  = (const float*)d_in[20];
    const float* b1   = (const float*)d_in[21];
    float* out = (float*)d_out;

    float* traj_hs;
    float* graph_hs;
    if (out_size >= ENC_ELEMS + 2*SEQ_ELEMS) {
        graph_hs = out + ENC_ELEMS;
        traj_hs  = out + ENC_ELEMS + SEQ_ELEMS;
    } else {
        void* pt = nullptr; void* pg = nullptr;
        cudaGetSymbolAddress(&pt, g_traj_fb);
        cudaGetSymbolAddress(&pg, g_graph_fb);
        traj_hs  = (float*)pt;
        graph_hs = (float*)pg;
    }

    lstm_traj_kernel<<<NN/32, 256>>>(obs, h0t, c0t, WihT, WhhT, bihT, bhhT, traj_hs);
    gat0_kernel<<<SS*TT, 256>>>(traj_hs, w0, as0, ad0, b0);
    gat1_kernel<<<SS*TT, 256>>>(w1, as1, ad1, b1);
    lstm_graph_kernel<<<NN/32, 256>>>(h0g, c0g, WihG, WhhG, bihG, bhhG, graph_hs);
    concat_kernel<<<(NN*18 + 255)/256, 256>>>(z, traj_hs, graph_hs, out);
}